// round 2
// baseline (speedup 1.0000x reference)
#include <cuda_runtime.h>
#include <cuda_bf16.h>

#define BD 512
#define DD 512
#define NL 3
#define NK 100
#define NTHREADS 256

// One block per batch row. h for that row lives in shared memory across all
// 3 layers. The phi spline (uniform knots) is evaluated via a 32-way
// lane-replicated (c, dc) float2 table for conflict-free LDS.64 gathers.
__global__ __launch_bounds__(NTHREADS) void sprecher_kernel(
    const float* __restrict__ x,
    const float* __restrict__ lambdas,
    const float* __restrict__ eta,
    const float* __restrict__ phi_log_inc,
    const float* __restrict__ Phi_coeffs,
    const float* __restrict__ dc_p, const float* __restrict__ dr_p,
    const float* __restrict__ cc_p, const float* __restrict__ cr_p,
    const float* __restrict__ res_w,
    const float* __restrict__ output_scale,
    float* __restrict__ out)
{
    __shared__ float h[DD];
    __shared__ float lam[DD];
    __shared__ float2 phi_tab[99 * 32];   // lane-replicated (c[k], c[k+1]-c[k])
    __shared__ float Phic[NK];
    __shared__ float coef[NK];
    __shared__ float s_cmin, s_cmax, s_inv;
    __shared__ float red[NTHREADS / 32];

    const int b    = blockIdx.x;
    const int tid  = threadIdx.x;
    const int lane = tid & 31;

    // Load input row into shared h
    for (int i = tid; i < DD; i += NTHREADS) h[i] = x[b * DD + i];

    const float dcv = dc_p[0], drv = dr_p[0], ccv = cc_p[0], crv = cr_p[0];
    const float in_min = dcv - drv, in_max = dcv + drv;
    const float o_min  = ccv - crv, o_max  = ccv + crv;
    const float cap_scale = 99.0f / (in_max - in_min);

    for (int l = 0; l < NL; ++l) {
        const float etal = eta[l];
        const float rw   = res_w[l];

        __syncthreads();  // prior layer's h writes / table reads complete
        // Stage per-layer tables
        if (tid < NK) {
            float v = phi_log_inc[l * NK + tid];
            coef[tid] = (v > 20.f) ? v : log1pf(expf(v));   // softplus
            Phic[tid] = Phi_coeffs[l * NK + tid];
        }
        for (int i = tid; i < DD; i += NTHREADS) lam[i] = lambdas[l * DD + i];
        __syncthreads();

        if (tid == 0) {
            float cum = 0.f;
            float mn = Phic[0], mx = Phic[0];
            for (int k = 0; k < NK; ++k) {
                cum += coef[k];
                coef[k] = cum;
                float p = Phic[k];
                mn = fminf(mn, p);
                mx = fmaxf(mx, p);
            }
            s_inv  = 1.0f / (cum + 1e-8f);
            s_cmin = mn;
            s_cmax = mx;
        }
        __syncthreads();

        {   // Build lane-replicated pair table
            const float inv = s_inv;
            for (int idx = tid; idx < 99 * 32; idx += NTHREADS) {
                int k = idx >> 5;
                float c0 = coef[k] * inv;
                float c1 = coef[k + 1] * inv;
                phi_tab[idx] = make_float2(c0, c1 - c0);
            }
        }
        __syncthreads();

        // Main contraction: each thread owns outputs o0=tid and o1=tid+256
        const float co0 = etal * (float)tid;
        const float co1 = etal * (float)(tid + NTHREADS);
        float acc0 = 0.f, acc1 = 0.f;

        #pragma unroll 4
        for (int i = 0; i < DD; ++i) {
            const float hv = h[i];      // broadcast
            const float li = lam[i];    // broadcast
            {
                float xx = fminf(fmaxf(hv + co0, 0.f), 1.f);
                float u  = xx * 99.0f;
                int   k  = (int)u; k = min(k, 98);
                float f  = u - (float)k;
                float2 p = phi_tab[(k << 5) | lane];
                acc0 = fmaf(li, fmaf(f, p.y, p.x), acc0);
            }
            {
                float xx = fminf(fmaxf(hv + co1, 0.f), 1.f);
                float u  = xx * 99.0f;
                int   k  = (int)u; k = min(k, 98);
                float f  = u - (float)k;
                float2 p = phi_tab[(k << 5) | lane];
                acc1 = fmaf(li, fmaf(f, p.y, p.x), acc1);
            }
        }

        // Epilogue: Phi spline + renorm + residual
        const float cmin = s_cmin, cmax = s_cmax;
        const float inv_norm = 1.0f / (cmax - cmin + 1e-8f);
        float act0, act1;
        {
            float s   = acc0 + (float)tid;              // + q[o0]
            float scv = fminf(fmaxf(s, in_min), in_max);
            float u   = (scv - in_min) * cap_scale;
            int   k   = (int)u; k = min(k, 98);
            float f   = u - (float)k;
            float c0  = Phic[k], c1 = Phic[k + 1];
            float raw = fmaf(f, c1 - c0, c0);
            float rn  = fminf(fmaxf((raw - cmin) * inv_norm, 0.f), 1.f);
            act0 = fmaf(o_max - o_min, rn, o_min) + rw * h[tid];
        }
        {
            float s   = acc1 + (float)(tid + NTHREADS); // + q[o1]
            float scv = fminf(fmaxf(s, in_min), in_max);
            float u   = (scv - in_min) * cap_scale;
            int   k   = (int)u; k = min(k, 98);
            float f   = u - (float)k;
            float c0  = Phic[k], c1 = Phic[k + 1];
            float raw = fmaf(f, c1 - c0, c0);
            float rn  = fminf(fmaxf((raw - cmin) * inv_norm, 0.f), 1.f);
            act1 = fmaf(o_max - o_min, rn, o_min) + rw * h[tid + NTHREADS];
        }

        if (l < NL - 1) {
            __syncthreads();            // all h reads done
            h[tid]            = act0;
            h[tid + NTHREADS] = act1;
        } else {
            // Final layer: sum over o, scale, write out[b]
            float v = act0 + act1;
            #pragma unroll
            for (int off = 16; off > 0; off >>= 1)
                v += __shfl_xor_sync(0xffffffffu, v, off);
            if (lane == 0) red[tid >> 5] = v;
            __syncthreads();
            if (tid == 0) {
                float r = 0.f;
                #pragma unroll
                for (int w = 0; w < NTHREADS / 32; ++w) r += red[w];
                out[b] = r * output_scale[0];
            }
        }
    }
}

extern "C" void kernel_launch(void* const* d_in, const int* in_sizes, int n_in,
                              void* d_out, int out_size)
{
    const float* x            = (const float*)d_in[0];
    const float* lambdas      = (const float*)d_in[1];
    const float* eta          = (const float*)d_in[2];
    const float* phi_log_inc  = (const float*)d_in[3];
    const float* Phi_coeffs   = (const float*)d_in[4];
    const float* dc           = (const float*)d_in[5];
    const float* dr           = (const float*)d_in[6];
    const float* cc           = (const float*)d_in[7];
    const float* cr           = (const float*)d_in[8];
    const float* res_w        = (const float*)d_in[9];
    const float* output_scale = (const float*)d_in[10];
    float* out = (float*)d_out;

    sprecher_kernel<<<BD, NTHREADS>>>(x, lambdas, eta, phi_log_inc, Phi_coeffs,
                                      dc, dr, cc, cr, res_w, output_scale, out);
}

// round 3
// speedup vs baseline: 1.2035x; 1.2035x over previous
#include <cuda_runtime.h>
#include <cuda_bf16.h>

#define BD 512
#define DD 512
#define NL 3
#define NK 100
#define NTHREADS 256
#define UMAX 98.999992f

// One block per batch row; h lives in smem across all 3 layers.
// phi spline: 32-way lane-replicated fma-form table (dc_k, c0_k - k*dc_k)
// so phi(u) = fmaf(u, t.x, t.y) with u = clamp(h*99 + eta*o*99, 0, ~99).
__global__ __launch_bounds__(NTHREADS) void sprecher_kernel(
    const float* __restrict__ x,
    const float* __restrict__ lambdas,
    const float* __restrict__ eta,
    const float* __restrict__ phi_log_inc,
    const float* __restrict__ Phi_coeffs,
    const float* __restrict__ dc_p, const float* __restrict__ dr_p,
    const float* __restrict__ cc_p, const float* __restrict__ cr_p,
    const float* __restrict__ res_w,
    const float* __restrict__ output_scale,
    float* __restrict__ out)
{
    __shared__ float  h[DD];              // raw activations (for residual)
    __shared__ float2 hl[DD];             // (h*99, lambda_l)
    __shared__ float2 phi_tab[99 * 32];   // lane-replicated (dc, c0 - k*dc)
    __shared__ float  Phic[NK];
    __shared__ float  coef[NK];
    __shared__ float  s_cmin, s_cmax, s_inv;
    __shared__ float  red[NTHREADS / 32];

    const int b    = blockIdx.x;
    const int tid  = threadIdx.x;
    const int lane = tid & 31;

    for (int i = tid; i < DD; i += NTHREADS) h[i] = x[b * DD + i];

    const float dcv = dc_p[0], drv = dr_p[0], ccv = cc_p[0], crv = cr_p[0];
    const float in_min = dcv - drv, in_max = dcv + drv;
    const float o_min  = ccv - crv, o_max  = ccv + crv;
    const float cap_scale = 99.0f / (in_max - in_min);

    for (int l = 0; l < NL; ++l) {
        const float etal = eta[l];
        const float rw   = res_w[l];

        __syncthreads();  // prior h writes / table reads complete
        if (tid < NK) {
            float v = phi_log_inc[l * NK + tid];
            coef[tid] = (v > 20.f) ? v : log1pf(expf(v));   // softplus
            Phic[tid] = Phi_coeffs[l * NK + tid];
        }
        // pack (h*99, lambda) broadcast pairs
        for (int i = tid; i < DD; i += NTHREADS)
            hl[i] = make_float2(h[i] * 99.0f, lambdas[l * DD + i]);
        __syncthreads();

        if (tid == 0) {
            float cum = 0.f;
            float mn = Phic[0], mx = Phic[0];
            for (int k = 0; k < NK; ++k) {
                cum += coef[k];
                coef[k] = cum;
                float p = Phic[k];
                mn = fminf(mn, p);
                mx = fmaxf(mx, p);
            }
            s_inv  = 1.0f / (cum + 1e-8f);
            s_cmin = mn;
            s_cmax = mx;
        }
        __syncthreads();

        {   // lane-replicated fma-form table
            const float inv = s_inv;
            for (int idx = tid; idx < 99 * 32; idx += NTHREADS) {
                int k = idx >> 5;
                float c0 = coef[k] * inv;
                float dk = coef[k + 1] * inv - c0;
                phi_tab[idx] = make_float2(dk, fmaf(-(float)k, dk, c0));
            }
        }
        __syncthreads();

        const float co0 = etal * 99.0f * (float)tid;
        const float co1 = etal * 99.0f * (float)(tid + NTHREADS);
        float acc0 = 0.f, acc1 = 0.f;

        #pragma unroll 8
        for (int i = 0; i < DD; ++i) {
            const float2 hv = hl[i];    // one LDS.64 broadcast
            {
                float u = fminf(fmaxf(hv.x + co0, 0.f), UMAX);
                int   k = (int)u;
                float2 t = phi_tab[(k << 5) | lane];
                acc0 = fmaf(hv.y, fmaf(u, t.x, t.y), acc0);
            }
            {
                float u = fminf(fmaxf(hv.x + co1, 0.f), UMAX);
                int   k = (int)u;
                float2 t = phi_tab[(k << 5) | lane];
                acc1 = fmaf(hv.y, fmaf(u, t.x, t.y), acc1);
            }
        }

        // Epilogue: Phi spline + renorm + residual (2 evals/thread, cheap)
        const float cmin = s_cmin, cmax = s_cmax;
        const float inv_norm = 1.0f / (cmax - cmin + 1e-8f);
        float act0, act1;
        {
            float s   = acc0 + (float)tid;
            float scv = fminf(fmaxf(s, in_min), in_max);
            float u   = (scv - in_min) * cap_scale;
            int   k   = (int)u; k = min(k, 98);
            float f   = u - (float)k;
            float c0  = Phic[k], c1 = Phic[k + 1];
            float raw = fmaf(f, c1 - c0, c0);
            float rn  = fminf(fmaxf((raw - cmin) * inv_norm, 0.f), 1.f);
            act0 = fmaf(o_max - o_min, rn, o_min) + rw * h[tid];
        }
        {
            float s   = acc1 + (float)(tid + NTHREADS);
            float scv = fminf(fmaxf(s, in_min), in_max);
            float u   = (scv - in_min) * cap_scale;
            int   k   = (int)u; k = min(k, 98);
            float f   = u - (float)k;
            float c0  = Phic[k], c1 = Phic[k + 1];
            float raw = fmaf(f, c1 - c0, c0);
            float rn  = fminf(fmaxf((raw - cmin) * inv_norm, 0.f), 1.f);
            act1 = fmaf(o_max - o_min, rn, o_min) + rw * h[tid + NTHREADS];
        }

        if (l < NL - 1) {
            __syncthreads();
            h[tid]            = act0;
            h[tid + NTHREADS] = act1;
        } else {
            float v = act0 + act1;
            #pragma unroll
            for (int off = 16; off > 0; off >>= 1)
                v += __shfl_xor_sync(0xffffffffu, v, off);
            if (lane == 0) red[tid >> 5] = v;
            __syncthreads();
            if (tid == 0) {
                float r = 0.f;
                #pragma unroll
                for (int w = 0; w < NTHREADS / 32; ++w) r += red[w];
                out[b] = r * output_scale[0];
            }
        }
    }
}

extern "C" void kernel_launch(void* const* d_in, const int* in_sizes, int n_in,
                              void* d_out, int out_size)
{
    const float* x            = (const float*)d_in[0];
    const float* lambdas      = (const float*)d_in[1];
    const float* eta          = (const float*)d_in[2];
    const float* phi_log_inc  = (const float*)d_in[3];
    const float* Phi_coeffs   = (const float*)d_in[4];
    const float* dc           = (const float*)d_in[5];
    const float* dr           = (const float*)d_in[6];
    const float* cc           = (const float*)d_in[7];
    const float* cr           = (const float*)d_in[8];
    const float* res_w        = (const float*)d_in[9];
    const float* output_scale = (const float*)d_in[10];
    float* out = (float*)d_out;

    sprecher_kernel<<<BD, NTHREADS>>>(x, lambdas, eta, phi_log_inc, Phi_coeffs,
                                      dc, dr, cc, cr, res_w, output_scale, out);
}

// round 4
// speedup vs baseline: 1.2654x; 1.0515x over previous
#include <cuda_runtime.h>
#include <cuda_bf16.h>

#define BD 512
#define DD 512
#define NL 3
#define NK 100
#define NTHREADS 256
#define BETA 98.999992f

// One block per batch row; h lives in smem across all 3 layers.
// phi spline in saturate form: x = __saturatef(h + eta*o)  (FADD.SAT),
// u = x*BETA (k = (int)u <= 98 guaranteed), phi = fmaf(u, A_k, B_k) with
// A_k = dc_k*(99/BETA), B_k = c0_k - k*dc_k, from a 32-way lane-replicated
// table (conflict-free 2-phase LDS.64 gather).
__global__ __launch_bounds__(NTHREADS) void sprecher_kernel(
    const float* __restrict__ x,
    const float* __restrict__ lambdas,
    const float* __restrict__ eta,
    const float* __restrict__ phi_log_inc,
    const float* __restrict__ Phi_coeffs,
    const float* __restrict__ dc_p, const float* __restrict__ dr_p,
    const float* __restrict__ cc_p, const float* __restrict__ cr_p,
    const float* __restrict__ res_w,
    const float* __restrict__ output_scale,
    float* __restrict__ out)
{
    __shared__ float  h[DD];              // raw activations (residual + rebuild)
    __shared__ float4 hl4[DD / 2];        // (h_2i, lam_2i, h_2i+1, lam_2i+1)
    __shared__ float2 phi_tab[99 * 32];   // lane-replicated (A_k, B_k)
    __shared__ float  Phic[NK];
    __shared__ float  coef[NK];
    __shared__ float  s_cmin, s_cmax, s_inv;
    __shared__ float  red[NTHREADS / 32];

    const int b    = blockIdx.x;
    const int tid  = threadIdx.x;
    const int lane = tid & 31;

    for (int i = tid; i < DD; i += NTHREADS) h[i] = x[b * DD + i];

    const float dcv = dc_p[0], drv = dr_p[0], ccv = cc_p[0], crv = cr_p[0];
    const float in_min = dcv - drv, in_max = dcv + drv;
    const float o_min  = ccv - crv, o_max  = ccv + crv;
    const float cap_scale = 99.0f / (in_max - in_min);

    const float2* __restrict__ tabL = (const float2*)phi_tab + lane;

    for (int l = 0; l < NL; ++l) {
        const float etal = eta[l];
        const float rw   = res_w[l];

        __syncthreads();  // prior h writes / table reads complete
        if (tid < NK) {
            float v = phi_log_inc[l * NK + tid];
            coef[tid] = (v > 20.f) ? v : log1pf(expf(v));   // softplus
            Phic[tid] = Phi_coeffs[l * NK + tid];
        }
        __syncthreads();

        // pack (h, lambda) broadcast quads: one entry per thread
        {
            const float2 lm = ((const float2*)(lambdas + l * DD))[tid];
            hl4[tid] = make_float4(h[2 * tid], lm.x, h[2 * tid + 1], lm.y);
        }

        if (tid == 0) {
            float cum = 0.f;
            float mn = Phic[0], mx = Phic[0];
            for (int k = 0; k < NK; ++k) {
                cum += coef[k];
                coef[k] = cum;
                float p = Phic[k];
                mn = fminf(mn, p);
                mx = fmaxf(mx, p);
            }
            s_inv  = 1.0f / (cum + 1e-8f);
            s_cmin = mn;
            s_cmax = mx;
        }
        __syncthreads();

        {   // lane-replicated table: A_k = dc*(99/BETA), B_k = c0 - k*dc
            const float inv = s_inv;
            const float fix = 99.0f / BETA;
            for (int idx = tid; idx < 99 * 32; idx += NTHREADS) {
                int k = idx >> 5;
                float c0 = coef[k] * inv;
                float dk = coef[k + 1] * inv - c0;
                phi_tab[idx] = make_float2(dk * fix, fmaf(-(float)k, dk, c0));
            }
        }
        __syncthreads();

        const float co0 = etal * (float)tid;
        const float co1 = etal * (float)(tid + NTHREADS);
        float acc0 = 0.f, acc1 = 0.f;

        #pragma unroll 4
        for (int i2 = 0; i2 < DD / 2; ++i2) {
            const float4 hv = hl4[i2];   // one LDS.128 broadcast, two i's
            {
                float u = __saturatef(hv.x + co0) * BETA;
                float2 t = tabL[((int)u) * 32];
                acc0 = fmaf(hv.y, fmaf(u, t.x, t.y), acc0);
            }
            {
                float u = __saturatef(hv.x + co1) * BETA;
                float2 t = tabL[((int)u) * 32];
                acc1 = fmaf(hv.y, fmaf(u, t.x, t.y), acc1);
            }
            {
                float u = __saturatef(hv.z + co0) * BETA;
                float2 t = tabL[((int)u) * 32];
                acc0 = fmaf(hv.w, fmaf(u, t.x, t.y), acc0);
            }
            {
                float u = __saturatef(hv.z + co1) * BETA;
                float2 t = tabL[((int)u) * 32];
                acc1 = fmaf(hv.w, fmaf(u, t.x, t.y), acc1);
            }
        }

        // Epilogue: Phi spline + renorm + residual (2 evals/thread, cheap)
        const float cmin = s_cmin, cmax = s_cmax;
        const float inv_norm = 1.0f / (cmax - cmin + 1e-8f);
        float act0, act1;
        {
            float s   = acc0 + (float)tid;
            float scv = fminf(fmaxf(s, in_min), in_max);
            float u   = (scv - in_min) * cap_scale;
            int   k   = (int)u; k = min(k, 98);
            float f   = u - (float)k;
            float c0  = Phic[k], c1 = Phic[k + 1];
            float raw = fmaf(f, c1 - c0, c0);
            float rn  = fminf(fmaxf((raw - cmin) * inv_norm, 0.f), 1.f);
            act0 = fmaf(o_max - o_min, rn, o_min) + rw * h[tid];
        }
        {
            float s   = acc1 + (float)(tid + NTHREADS);
            float scv = fminf(fmaxf(s, in_min), in_max);
            float u   = (scv - in_min) * cap_scale;
            int   k   = (int)u; k = min(k, 98);
            float f   = u - (float)k;
            float c0  = Phic[k], c1 = Phic[k + 1];
            float raw = fmaf(f, c1 - c0, c0);
            float rn  = fminf(fmaxf((raw - cmin) * inv_norm, 0.f), 1.f);
            act1 = fmaf(o_max - o_min, rn, o_min) + rw * h[tid + NTHREADS];
        }

        if (l < NL - 1) {
            __syncthreads();
            h[tid]            = act0;
            h[tid + NTHREADS] = act1;
        } else {
            float v = act0 + act1;
            #pragma unroll
            for (int off = 16; off > 0; off >>= 1)
                v += __shfl_xor_sync(0xffffffffu, v, off);
            if (lane == 0) red[tid >> 5] = v;
            __syncthreads();
            if (tid == 0) {
                float r = 0.f;
                #pragma unroll
                for (int w = 0; w < NTHREADS / 32; ++w) r += red[w];
                out[b] = r * output_scale[0];
            }
        }
    }
}

extern "C" void kernel_launch(void* const* d_in, const int* in_sizes, int n_in,
                              void* d_out, int out_size)
{
    const float* x            = (const float*)d_in[0];
    const float* lambdas      = (const float*)d_in[1];
    const float* eta          = (const float*)d_in[2];
    const float* phi_log_inc  = (const float*)d_in[3];
    const float* Phi_coeffs   = (const float*)d_in[4];
    const float* dc           = (const float*)d_in[5];
    const float* dr           = (const float*)d_in[6];
    const float* cc           = (const float*)d_in[7];
    const float* cr           = (const float*)d_in[8];
    const float* res_w        = (const float*)d_in[9];
    const float* output_scale = (const float*)d_in[10];
    float* out = (float*)d_out;

    sprecher_kernel<<<BD, NTHREADS>>>(x, lambdas, eta, phi_log_inc, Phi_coeffs,
                                      dc, dr, cc, cr, res_w, output_scale, out);
}

// round 5
// speedup vs baseline: 3.5265x; 2.7868x over previous
#include <cuda_runtime.h>
#include <cuda_bf16.h>

#define BD 512
#define DD 512
#define NL 3
#define NK 100
#define NTHREADS 256
#define BETA 98.999992f

// One block per batch row; h lives in smem across all 3 layers.
// FAST PATH (detected at runtime): if all softplus increments of phi are equal
// (true for this dataset: phi_log_inc is a constant vector), the monotone
// spline collapses exactly to phi(x) = gamma*(1 + 99x) on [0,1], so the inner
// loop is FADD.SAT + FFMA per (i,o) eval with NO shared-memory gather.
// FALLBACK: lane-replicated (A_k,B_k) table with conflict-free LDS.64 gather.
__global__ __launch_bounds__(NTHREADS) void sprecher_kernel(
    const float* __restrict__ x,
    const float* __restrict__ lambdas,
    const float* __restrict__ eta,
    const float* __restrict__ phi_log_inc,
    const float* __restrict__ Phi_coeffs,
    const float* __restrict__ dc_p, const float* __restrict__ dr_p,
    const float* __restrict__ cc_p, const float* __restrict__ cr_p,
    const float* __restrict__ res_w,
    const float* __restrict__ output_scale,
    float* __restrict__ out)
{
    __shared__ float  h[DD];              // raw activations (residual + rebuild)
    __shared__ float4 hl4[DD / 2];        // (h_2i, lam_2i, h_2i+1, lam_2i+1)
    __shared__ float2 phi_tab[99 * 32];   // fallback: lane-replicated (A_k, B_k)
    __shared__ float  Phic[NK];
    __shared__ float  coef[NK];
    __shared__ float  s_cmin, s_cmax, s_inv, s_gamma, s_sumlam;
    __shared__ int    s_linear;
    __shared__ float  red[NTHREADS / 32];

    const int b    = blockIdx.x;
    const int tid  = threadIdx.x;
    const int lane = tid & 31;

    for (int i = tid; i < DD; i += NTHREADS) h[i] = x[b * DD + i];

    const float dcv = dc_p[0], drv = dr_p[0], ccv = cc_p[0], crv = cr_p[0];
    const float in_min = dcv - drv, in_max = dcv + drv;
    const float o_min  = ccv - crv, o_max  = ccv + crv;
    const float cap_scale = 99.0f / (in_max - in_min);

    const float2* __restrict__ tabL = (const float2*)phi_tab + lane;

    for (int l = 0; l < NL; ++l) {
        const float etal = eta[l];
        const float rw   = res_w[l];

        __syncthreads();  // prior h writes / table reads complete
        if (tid < NK) {
            float v = phi_log_inc[l * NK + tid];
            coef[tid] = (v > 20.f) ? v : log1pf(expf(v));   // softplus
            Phic[tid] = Phi_coeffs[l * NK + tid];
        }
        __syncthreads();

        // pack (h, lambda) broadcast quads + per-thread lambda partial sum
        float lpart;
        {
            const float2 lm = ((const float2*)(lambdas + l * DD))[tid];
            hl4[tid] = make_float4(h[2 * tid], lm.x, h[2 * tid + 1], lm.y);
            lpart = lm.x + lm.y;
        }
        #pragma unroll
        for (int off = 16; off > 0; off >>= 1)
            lpart += __shfl_xor_sync(0xffffffffu, lpart, off);
        if (lane == 0) red[tid >> 5] = lpart;

        __syncthreads();
        if (tid == 0) {
            float cum = 0.f;
            float mn = Phic[0], mx = Phic[0];
            const float i0 = coef[0];
            int lin = 1;
            for (int k = 0; k < NK; ++k) {
                float ck = coef[k];
                if (fabsf(ck - i0) > 1e-6f * fabsf(i0)) lin = 0;
                cum += ck;
                coef[k] = cum;
                float p = Phic[k];
                mn = fminf(mn, p);
                mx = fmaxf(mx, p);
            }
            s_inv    = 1.0f / (cum + 1e-8f);
            s_gamma  = i0 / (cum + 1e-8f);
            s_linear = lin;
            s_cmin   = mn;
            s_cmax   = mx;
            float sl = 0.f;
            #pragma unroll
            for (int w = 0; w < NTHREADS / 32; ++w) sl += red[w];
            s_sumlam = sl;
        }
        __syncthreads();

        const int linear = s_linear;
        if (!linear) {   // build lane-replicated fallback table
            const float inv = s_inv;
            const float fix = 99.0f / BETA;
            for (int idx = tid; idx < 99 * 32; idx += NTHREADS) {
                int k = idx >> 5;
                float c0 = coef[k] * inv;
                float dk = coef[k + 1] * inv - c0;
                phi_tab[idx] = make_float2(dk * fix, fmaf(-(float)k, dk, c0));
            }
            __syncthreads();
        }

        const float co0 = etal * (float)tid;
        const float co1 = etal * (float)(tid + NTHREADS);
        float acc0 = 0.f, acc1 = 0.f;

        if (linear) {
            #pragma unroll 8
            for (int i2 = 0; i2 < DD / 2; ++i2) {
                const float4 hv = hl4[i2];   // one LDS.128 broadcast, two i's
                acc0 = fmaf(hv.y, __saturatef(hv.x + co0), acc0);
                acc1 = fmaf(hv.y, __saturatef(hv.x + co1), acc1);
                acc0 = fmaf(hv.w, __saturatef(hv.z + co0), acc0);
                acc1 = fmaf(hv.w, __saturatef(hv.z + co1), acc1);
            }
            // Sum lam_i * phi = gamma*(sumlam + 99*acc)
            const float g99  = 99.0f * s_gamma;
            const float base = s_gamma * s_sumlam;
            acc0 = fmaf(g99, acc0, base);
            acc1 = fmaf(g99, acc1, base);
        } else {
            #pragma unroll 4
            for (int i2 = 0; i2 < DD / 2; ++i2) {
                const float4 hv = hl4[i2];
                {
                    float u = __saturatef(hv.x + co0) * BETA;
                    float2 t = tabL[((int)u) * 32];
                    acc0 = fmaf(hv.y, fmaf(u, t.x, t.y), acc0);
                }
                {
                    float u = __saturatef(hv.x + co1) * BETA;
                    float2 t = tabL[((int)u) * 32];
                    acc1 = fmaf(hv.y, fmaf(u, t.x, t.y), acc1);
                }
                {
                    float u = __saturatef(hv.z + co0) * BETA;
                    float2 t = tabL[((int)u) * 32];
                    acc0 = fmaf(hv.w, fmaf(u, t.x, t.y), acc0);
                }
                {
                    float u = __saturatef(hv.z + co1) * BETA;
                    float2 t = tabL[((int)u) * 32];
                    acc1 = fmaf(hv.w, fmaf(u, t.x, t.y), acc1);
                }
            }
        }

        // Epilogue: Phi spline + renorm + residual
        const float cmin = s_cmin, cmax = s_cmax;
        const float inv_norm = 1.0f / (cmax - cmin + 1e-8f);
        float act0, act1;
        {
            float s   = acc0 + (float)tid;
            float scv = fminf(fmaxf(s, in_min), in_max);
            float u   = (scv - in_min) * cap_scale;
            int   k   = (int)u; k = min(k, 98);
            float f   = u - (float)k;
            float c0  = Phic[k], c1 = Phic[k + 1];
            float raw = fmaf(f, c1 - c0, c0);
            float rn  = fminf(fmaxf((raw - cmin) * inv_norm, 0.f), 1.f);
            act0 = fmaf(o_max - o_min, rn, o_min) + rw * h[tid];
        }
        {
            float s   = acc1 + (float)(tid + NTHREADS);
            float scv = fminf(fmaxf(s, in_min), in_max);
            float u   = (scv - in_min) * cap_scale;
            int   k   = (int)u; k = min(k, 98);
            float f   = u - (float)k;
            float c0  = Phic[k], c1 = Phic[k + 1];
            float raw = fmaf(f, c1 - c0, c0);
            float rn  = fminf(fmaxf((raw - cmin) * inv_norm, 0.f), 1.f);
            act1 = fmaf(o_max - o_min, rn, o_min) + rw * h[tid + NTHREADS];
        }

        if (l < NL - 1) {
            __syncthreads();
            h[tid]            = act0;
            h[tid + NTHREADS] = act1;
        } else {
            float v = act0 + act1;
            #pragma unroll
            for (int off = 16; off > 0; off >>= 1)
                v += __shfl_xor_sync(0xffffffffu, v, off);
            if (lane == 0) red[tid >> 5] = v;
            __syncthreads();
            if (tid == 0) {
                float r = 0.f;
                #pragma unroll
                for (int w = 0; w < NTHREADS / 32; ++w) r += red[w];
                out[b] = r * output_scale[0];
            }
        }
    }
}

extern "C" void kernel_launch(void* const* d_in, const int* in_sizes, int n_in,
                              void* d_out, int out_size)
{
    const float* x            = (const float*)d_in[0];
    const float* lambdas      = (const float*)d_in[1];
    const float* eta          = (const float*)d_in[2];
    const float* phi_log_inc  = (const float*)d_in[3];
    const float* Phi_coeffs   = (const float*)d_in[4];
    const float* dc           = (const float*)d_in[5];
    const float* dr           = (const float*)d_in[6];
    const float* cc           = (const float*)d_in[7];
    const float* cr           = (const float*)d_in[8];
    const float* res_w        = (const float*)d_in[9];
    const float* output_scale = (const float*)d_in[10];
    float* out = (float*)d_out;

    sprecher_kernel<<<BD, NTHREADS>>>(x, lambdas, eta, phi_log_inc, Phi_coeffs,
                                      dc, dr, cc, cr, res_w, output_scale, out);
}